// round 3
// baseline (speedup 1.0000x reference)
#include <cuda_runtime.h>

// Problem constants
#define NN    2048          // meta nodes
#define MDIM  64            // subgraph nodes
#define DDIM  64            // channels
#define FDIM  4096          // MDIM*DDIM
#define OUTD  64
#define LN_EPS 1e-5f

// ------------------------- scratch (device globals; no allocation) ----------
__device__ float g_Af[NN * NN];
__device__ float g_A2[NN * NN];
__device__ float g_A3[NN * NN];
__device__ float g_X [NN * FDIM];
__device__ float g_B1[NN * FDIM];
__device__ float g_B2[NN * FDIM];
__device__ float g_Y [NN * FDIM];
__device__ float g_Sn[MDIM * MDIM];

// ------------------------- int32 -> float cast ------------------------------
__global__ void cast_i2f(const int* __restrict__ a, float* __restrict__ o) {
    int i = blockIdx.x * blockDim.x + threadIdx.x;
    o[i] = (float)a[i];
}

// ------------------------- Sn = D^-1/2 (S+I) D^-1/2 -------------------------
__global__ void compute_sn(const int* __restrict__ sub_adj, float* __restrict__ Sn) {
    __shared__ float dinv[MDIM];
    int u = threadIdx.x;                 // 64 threads
    float s = 1.0f;                      // self loop
    for (int v = 0; v < MDIM; v++) s += (float)sub_adj[u * MDIM + v];
    dinv[u] = rsqrtf(s);
    __syncthreads();
    float du = dinv[u];
    for (int v = 0; v < MDIM; v++) {
        float a = (float)sub_adj[u * MDIM + v] + (u == v ? 1.0f : 0.0f);
        Sn[u * MDIM + v] = du * a * dinv[v];
    }
}

// ------------------------- big SGEMM: C = A(MxK) * B(KxN) -------------------
// All dims multiples of tile sizes. 128x128x8, 256 threads, 8x8 per thread.
#define BM 128
#define BN 128
#define BK 8

__global__ __launch_bounds__(256, 2)
void sgemm128(const float* __restrict__ A, const float* __restrict__ B,
              float* __restrict__ C, int M, int N, int K) {
    __shared__ float As[BK][BM];
    __shared__ float Bs[BK][BN];

    const int bm = blockIdx.y * BM;
    const int bn = blockIdx.x * BN;
    const int t  = threadIdx.x;
    const int w    = t >> 5;
    const int lane = t & 31;
    // 8 warps: 4x2 warp grid, each warp 32 rows x 64 cols
    const int wr = w >> 1, wc = w & 1;
    const int lr = lane >> 3, lc = lane & 7;
    const int row0 = wr * 32 + lr * 8;
    const int col0 = wc * 64 + lc * 8;

    // load mapping
    const int arow = t >> 1;            // 0..127
    const int ac4  = (t & 1) * 4;       // 0 or 4
    const int brow = t >> 5;            // 0..7
    const int bc4  = (t & 31) * 4;      // 0..124

    const float* Aptr = A + (long)(bm + arow) * K + ac4;
    const float* Bptr = B + (long)brow * N + bn + bc4;

    float acc[8][8];
    #pragma unroll
    for (int i = 0; i < 8; i++)
        #pragma unroll
        for (int j = 0; j < 8; j++) acc[i][j] = 0.0f;

    float4 av = *(const float4*)(Aptr);
    float4 bv = *(const float4*)(Bptr);

    for (int k0 = 0; k0 < K; k0 += BK) {
        As[ac4 + 0][arow] = av.x;
        As[ac4 + 1][arow] = av.y;
        As[ac4 + 2][arow] = av.z;
        As[ac4 + 3][arow] = av.w;
        *(float4*)&Bs[brow][bc4] = bv;
        __syncthreads();

        if (k0 + BK < K) {                      // register prefetch of next tile
            av = *(const float4*)(Aptr + (k0 + BK));
            bv = *(const float4*)(Bptr + (long)(k0 + BK) * N);
        }

        #pragma unroll
        for (int kk = 0; kk < BK; kk++) {
            float a[8], b[8];
            *(float4*)(a)     = *(const float4*)&As[kk][row0];
            *(float4*)(a + 4) = *(const float4*)&As[kk][row0 + 4];
            *(float4*)(b)     = *(const float4*)&Bs[kk][col0];
            *(float4*)(b + 4) = *(const float4*)&Bs[kk][col0 + 4];
            #pragma unroll
            for (int i = 0; i < 8; i++)
                #pragma unroll
                for (int j = 0; j < 8; j++)
                    acc[i][j] += a[i] * b[j];
        }
        __syncthreads();
    }

    #pragma unroll
    for (int i = 0; i < 8; i++) {
        float4 v0 = make_float4(acc[i][0], acc[i][1], acc[i][2], acc[i][3]);
        float4 v1 = make_float4(acc[i][4], acc[i][5], acc[i][6], acc[i][7]);
        float* Cp = C + (long)(bm + row0 + i) * N + bn + col0;
        *(float4*)(Cp)     = v0;
        *(float4*)(Cp + 4) = v1;
    }
}

// ------------------- weight apply: Y(R,64) (+)= X(R,64) @ W(64,64) ----------
// grid: R/64 blocks, 256 threads
__global__ __launch_bounds__(256)
void wgemm64(const float* __restrict__ X, const float* __restrict__ W,
             float* __restrict__ Y, int accumulate) {
    __shared__ float Xs[64][68];
    __shared__ float Ws[64][64];
    const int t = threadIdx.x;
    const long row0 = (long)blockIdx.x * 64;

    #pragma unroll
    for (int i = 0; i < 16; i++) {
        int idx = t + i * 256;
        ((float*)Ws)[idx] = W[idx];
        int r = idx >> 6, c = idx & 63;
        Xs[r][c] = X[(row0 + r) * 64 + c];
    }
    __syncthreads();

    const int r  = t >> 2;
    const int c0 = (t & 3) * 16;
    float acc[16];
    if (accumulate) {
        #pragma unroll
        for (int q = 0; q < 4; q++)
            *(float4*)&acc[q * 4] = *(const float4*)(Y + (row0 + r) * 64 + c0 + q * 4);
    } else {
        #pragma unroll
        for (int j = 0; j < 16; j++) acc[j] = 0.0f;
    }
    #pragma unroll 8
    for (int d = 0; d < 64; d++) {
        float xv = Xs[r][d];
        #pragma unroll
        for (int j = 0; j < 16; j++) acc[j] += xv * Ws[d][c0 + j];
    }
    #pragma unroll
    for (int q = 0; q < 4; q++)
        *(float4*)(Y + (row0 + r) * 64 + c0 + q * 4) = *(float4*)&acc[q * 4];
}

// -------- per-n: H = Sn @ Y[n] + bias_sum ; LayerNorm(m,d) ; ReLU -> X ------
__global__ __launch_bounds__(256)
void sn_ln_relu(const float* __restrict__ Y, const float* __restrict__ Sn,
                const float* __restrict__ bconv_l,   // (4,64)
                const float* __restrict__ gamma_l,   // (64,64)
                const float* __restrict__ beta_l,    // (64,64)
                float* __restrict__ Xout) {
    __shared__ float Ys[64][68];
    __shared__ float Sns[64][68];
    __shared__ float red[8];
    __shared__ float s_mu, s_rstd;

    const int n = blockIdx.x;
    const int t = threadIdx.x;
    const float* Yn = Y + (long)n * FDIM;

    #pragma unroll
    for (int i = 0; i < 16; i++) {
        int idx = t + i * 256;
        int r = idx >> 6, c = idx & 63;
        Ys[r][c]  = Yn[idx];
        Sns[r][c] = Sn[idx];
    }
    __syncthreads();

    const int u  = t >> 2;
    const int c0 = (t & 3) * 16;

    float h[16];
    #pragma unroll
    for (int j = 0; j < 16; j++)
        h[j] = bconv_l[c0 + j] + bconv_l[64 + c0 + j] +
               bconv_l[128 + c0 + j] + bconv_l[192 + c0 + j];

    #pragma unroll 8
    for (int v = 0; v < 64; v++) {
        float s = Sns[u][v];
        #pragma unroll
        for (int j = 0; j < 16; j++) h[j] += s * Ys[v][c0 + j];
    }

    // block mean
    const int lane = t & 31, wid = t >> 5;
    float lsum = 0.0f;
    #pragma unroll
    for (int j = 0; j < 16; j++) lsum += h[j];
    #pragma unroll
    for (int o = 16; o > 0; o >>= 1) lsum += __shfl_xor_sync(0xffffffffu, lsum, o);
    if (lane == 0) red[wid] = lsum;
    __syncthreads();
    if (t == 0) {
        float s = 0.0f;
        #pragma unroll
        for (int i = 0; i < 8; i++) s += red[i];
        s_mu = s * (1.0f / 4096.0f);
    }
    __syncthreads();
    const float mu = s_mu;

    // block variance (two-pass, matches jnp.var)
    float lv = 0.0f;
    #pragma unroll
    for (int j = 0; j < 16; j++) { float d = h[j] - mu; lv += d * d; }
    #pragma unroll
    for (int o = 16; o > 0; o >>= 1) lv += __shfl_xor_sync(0xffffffffu, lv, o);
    if (lane == 0) red[wid] = lv;
    __syncthreads();
    if (t == 0) {
        float s = 0.0f;
        #pragma unroll
        for (int i = 0; i < 8; i++) s += red[i];
        s_rstd = rsqrtf(s * (1.0f / 4096.0f) + LN_EPS);
    }
    __syncthreads();
    const float rstd = s_rstd;

    float* Xn = Xout + (long)n * FDIM + u * 64 + c0;
    const float* gp = gamma_l + u * 64 + c0;
    const float* bp = beta_l  + u * 64 + c0;
    #pragma unroll
    for (int j = 0; j < 16; j++) {
        float v = (h[j] - mu) * rstd * gp[j] + bp[j];
        Xn[j] = fmaxf(v, 0.0f);
    }
}

// ----------- readout: out(2048,64) = X(2048,4096) @ Wl(4096,64) + bl --------
// grid: 2048/16 = 128 blocks, 256 threads
__global__ __launch_bounds__(256)
void final_gemm(const float* __restrict__ X, const float* __restrict__ Wl,
                const float* __restrict__ bl, float* __restrict__ out) {
    __shared__ float Xs[16][128];
    __shared__ float Ws[128][68];
    const int t = threadIdx.x;
    const long m0 = (long)blockIdx.x * 16;
    const int r  = t >> 4;          // 0..15
    const int cq = (t & 15) * 4;    // 0..60

    float acc[4] = {0.f, 0.f, 0.f, 0.f};

    for (int k0 = 0; k0 < FDIM; k0 += 128) {
        #pragma unroll
        for (int i = 0; i < 2; i++) {
            int idx = t + i * 256;              // float4 idx 0..511
            int rr = idx >> 5, cc = (idx & 31) * 4;
            *(float4*)&Xs[rr][cc] = *(const float4*)(X + (m0 + rr) * FDIM + k0 + cc);
        }
        #pragma unroll
        for (int i = 0; i < 8; i++) {
            int idx = t + i * 256;              // float4 idx 0..2047
            int kk = idx >> 4, cc = (idx & 15) * 4;
            float4 v = *(const float4*)(Wl + (long)(k0 + kk) * 64 + cc);
            Ws[kk][cc] = v.x; Ws[kk][cc + 1] = v.y; Ws[kk][cc + 2] = v.z; Ws[kk][cc + 3] = v.w;
        }
        __syncthreads();
        #pragma unroll 16
        for (int kk = 0; kk < 128; kk++) {
            float xv = Xs[r][kk];
            #pragma unroll
            for (int j = 0; j < 4; j++) acc[j] += xv * Ws[kk][cq + j];
        }
        __syncthreads();
    }
    float4 v = make_float4(acc[0] + bl[cq], acc[1] + bl[cq + 1],
                           acc[2] + bl[cq + 2], acc[3] + bl[cq + 3]);
    *(float4*)(out + (m0 + r) * 64 + cq) = v;
}

// ---------------------------------------------------------------------------
extern "C" void kernel_launch(void* const* d_in, const int* in_sizes, int n_in,
                              void* d_out, int out_size) {
    const float* x_in    = (const float*)d_in[0];   // (2048,64,64)
    const int*   sub_adj = (const int*)  d_in[1];   // (64,64)
    const int*   adj     = (const int*)  d_in[2];   // (2048,2048)
    const float* W_convs = (const float*)d_in[3];   // (3,4,64,64)
    const float* b_convs = (const float*)d_in[4];   // (3,4,64)
    const float* ln_g    = (const float*)d_in[5];   // (3,64,64)
    const float* ln_b    = (const float*)d_in[6];   // (3,64,64)
    const float* W_lin   = (const float*)d_in[7];   // (4096,64)
    const float* b_lin   = (const float*)d_in[8];   // (64)
    float* out = (float*)d_out;

    float *Af, *A2, *A3, *X, *B1, *B2, *Y, *Sn;
    cudaGetSymbolAddress((void**)&Af, g_Af);
    cudaGetSymbolAddress((void**)&A2, g_A2);
    cudaGetSymbolAddress((void**)&A3, g_A3);
    cudaGetSymbolAddress((void**)&X,  g_X);
    cudaGetSymbolAddress((void**)&B1, g_B1);
    cudaGetSymbolAddress((void**)&B2, g_B2);
    cudaGetSymbolAddress((void**)&Y,  g_Y);
    cudaGetSymbolAddress((void**)&Sn, g_Sn);

    // precompute: A as float, A^2, A^3, Sn
    cast_i2f<<<(NN * NN) / 256, 256>>>(adj, Af);
    sgemm128<<<dim3(NN / BN, NN / BM), 256>>>(Af, Af, A2, NN, NN, NN);
    sgemm128<<<dim3(NN / BN, NN / BM), 256>>>(A2, Af, A3, NN, NN, NN);
    compute_sn<<<1, 64>>>(sub_adj, Sn);

    const int RB = (NN * MDIM) / 64;   // wgemm blocks = 2048
    for (int l = 0; l < 3; l++) {
        const float* curX = (l == 0) ? x_in : X;
        const float* Wl = W_convs + (long)l * 4 * 4096;

        // Y = curX @ W0
        wgemm64<<<RB, 256>>>(curX, Wl + 0 * 4096, Y, 0);
        // x1 = A @ x ; Y += x1 @ W1
        sgemm128<<<dim3(FDIM / BN, NN / BM), 256>>>(Af, curX, B1, NN, FDIM, NN);
        wgemm64<<<RB, 256>>>(B1, Wl + 1 * 4096, Y, 1);
        // x2 = A^2 @ x1 ; Y += x2 @ W2
        sgemm128<<<dim3(FDIM / BN, NN / BM), 256>>>(A2, B1, B2, NN, FDIM, NN);
        wgemm64<<<RB, 256>>>(B2, Wl + 2 * 4096, Y, 1);
        // x3 = A^3 @ x2 ; Y += x3 @ W3
        sgemm128<<<dim3(FDIM / BN, NN / BM), 256>>>(A3, B2, B1, NN, FDIM, NN);
        wgemm64<<<RB, 256>>>(B1, Wl + 3 * 4096, Y, 1);

        // X = relu(LN(Sn @ Y + sum_i b_i))
        sn_ln_relu<<<NN, 256>>>(Y, Sn,
                                b_convs + (long)l * 256,
                                ln_g + (long)l * 4096,
                                ln_b + (long)l * 4096,
                                X);
    }

    final_gemm<<<NN / 16, 256>>>(X, W_lin, b_lin, out);
}

// round 4
// speedup vs baseline: 1.0007x; 1.0007x over previous
#include <cuda_runtime.h>

// Problem constants
#define NN    2048          // meta nodes
#define MDIM  64            // subgraph nodes
#define DDIM  64            // channels
#define FDIM  4096          // MDIM*DDIM
#define OUTD  64
#define LN_EPS 1e-5f

// ------------------------- scratch (device globals; no allocation) ----------
__device__ float g_Af[NN * NN];
__device__ float g_A2[NN * NN];
__device__ float g_A3[NN * NN];
__device__ float g_X [NN * FDIM];
__device__ float g_B1[NN * FDIM];
__device__ float g_B2[NN * FDIM];
__device__ float g_Y [NN * FDIM];
__device__ float g_Sn[MDIM * MDIM];

// ------------------------- int32 -> float cast ------------------------------
__global__ void cast_i2f(const int* __restrict__ a, float* __restrict__ o) {
    int i = blockIdx.x * blockDim.x + threadIdx.x;
    o[i] = (float)a[i];
}

// ------------------------- Sn = D^-1/2 (S+I) D^-1/2 -------------------------
__global__ void compute_sn(const int* __restrict__ sub_adj, float* __restrict__ Sn) {
    __shared__ float dinv[MDIM];
    int u = threadIdx.x;                 // 64 threads
    float s = 1.0f;                      // self loop
    for (int v = 0; v < MDIM; v++) s += (float)sub_adj[u * MDIM + v];
    dinv[u] = rsqrtf(s);
    __syncthreads();
    float du = dinv[u];
    for (int v = 0; v < MDIM; v++) {
        float a = (float)sub_adj[u * MDIM + v] + (u == v ? 1.0f : 0.0f);
        Sn[u * MDIM + v] = du * a * dinv[v];
    }
}

// ------------------------- big SGEMM: C = A(MxK) * B(KxN) -------------------
// All dims multiples of tile sizes. 128x128x8, 256 threads, 8x8 per thread.
#define BM 128
#define BN 128
#define BK 8

__global__ __launch_bounds__(256, 2)
void sgemm128(const float* __restrict__ A, const float* __restrict__ B,
              float* __restrict__ C, int M, int N, int K) {
    __shared__ float As[BK][BM];
    __shared__ float Bs[BK][BN];

    const int bm = blockIdx.y * BM;
    const int bn = blockIdx.x * BN;
    const int t  = threadIdx.x;
    const int w    = t >> 5;
    const int lane = t & 31;
    // 8 warps: 4x2 warp grid, each warp 32 rows x 64 cols
    const int wr = w >> 1, wc = w & 1;
    const int lr = lane >> 3, lc = lane & 7;
    const int row0 = wr * 32 + lr * 8;
    const int col0 = wc * 64 + lc * 8;

    // load mapping
    const int arow = t >> 1;            // 0..127
    const int ac4  = (t & 1) * 4;       // 0 or 4
    const int brow = t >> 5;            // 0..7
    const int bc4  = (t & 31) * 4;      // 0..124

    const float* Aptr = A + (long)(bm + arow) * K + ac4;
    const float* Bptr = B + (long)brow * N + bn + bc4;

    float acc[8][8];
    #pragma unroll
    for (int i = 0; i < 8; i++)
        #pragma unroll
        for (int j = 0; j < 8; j++) acc[i][j] = 0.0f;

    float4 av = *(const float4*)(Aptr);
    float4 bv = *(const float4*)(Bptr);

    for (int k0 = 0; k0 < K; k0 += BK) {
        As[ac4 + 0][arow] = av.x;
        As[ac4 + 1][arow] = av.y;
        As[ac4 + 2][arow] = av.z;
        As[ac4 + 3][arow] = av.w;
        *(float4*)&Bs[brow][bc4] = bv;
        __syncthreads();

        if (k0 + BK < K) {                      // register prefetch of next tile
            av = *(const float4*)(Aptr + (k0 + BK));
            bv = *(const float4*)(Bptr + (long)(k0 + BK) * N);
        }

        #pragma unroll
        for (int kk = 0; kk < BK; kk++) {
            float a[8], b[8];
            *(float4*)(a)     = *(const float4*)&As[kk][row0];
            *(float4*)(a + 4) = *(const float4*)&As[kk][row0 + 4];
            *(float4*)(b)     = *(const float4*)&Bs[kk][col0];
            *(float4*)(b + 4) = *(const float4*)&Bs[kk][col0 + 4];
            #pragma unroll
            for (int i = 0; i < 8; i++)
                #pragma unroll
                for (int j = 0; j < 8; j++)
                    acc[i][j] += a[i] * b[j];
        }
        __syncthreads();
    }

    #pragma unroll
    for (int i = 0; i < 8; i++) {
        float4 v0 = make_float4(acc[i][0], acc[i][1], acc[i][2], acc[i][3]);
        float4 v1 = make_float4(acc[i][4], acc[i][5], acc[i][6], acc[i][7]);
        float* Cp = C + (long)(bm + row0 + i) * N + bn + col0;
        *(float4*)(Cp)     = v0;
        *(float4*)(Cp + 4) = v1;
    }
}

// ------------------- weight apply: Y(R,64) (+)= X(R,64) @ W(64,64) ----------
// grid: R/64 blocks, 256 threads
__global__ __launch_bounds__(256)
void wgemm64(const float* __restrict__ X, const float* __restrict__ W,
             float* __restrict__ Y, int accumulate) {
    __shared__ float Xs[64][68];
    __shared__ float Ws[64][64];
    const int t = threadIdx.x;
    const long row0 = (long)blockIdx.x * 64;

    #pragma unroll
    for (int i = 0; i < 16; i++) {
        int idx = t + i * 256;
        ((float*)Ws)[idx] = W[idx];
        int r = idx >> 6, c = idx & 63;
        Xs[r][c] = X[(row0 + r) * 64 + c];
    }
    __syncthreads();

    const int r  = t >> 2;
    const int c0 = (t & 3) * 16;
    float acc[16];
    if (accumulate) {
        #pragma unroll
        for (int q = 0; q < 4; q++)
            *(float4*)&acc[q * 4] = *(const float4*)(Y + (row0 + r) * 64 + c0 + q * 4);
    } else {
        #pragma unroll
        for (int j = 0; j < 16; j++) acc[j] = 0.0f;
    }
    #pragma unroll 8
    for (int d = 0; d < 64; d++) {
        float xv = Xs[r][d];
        #pragma unroll
        for (int j = 0; j < 16; j++) acc[j] += xv * Ws[d][c0 + j];
    }
    #pragma unroll
    for (int q = 0; q < 4; q++)
        *(float4*)(Y + (row0 + r) * 64 + c0 + q * 4) = *(float4*)&acc[q * 4];
}

// -------- per-n: H = Sn @ Y[n] + bias_sum ; LayerNorm(m,d) ; ReLU -> X ------
__global__ __launch_bounds__(256)
void sn_ln_relu(const float* __restrict__ Y, const float* __restrict__ Sn,
                const float* __restrict__ bconv_l,   // (4,64)
                const float* __restrict__ gamma_l,   // (64,64)
                const float* __restrict__ beta_l,    // (64,64)
                float* __restrict__ Xout) {
    __shared__ float Ys[64][68];
    __shared__ float Sns[64][68];
    __shared__ float red[8];
    __shared__ float s_mu, s_rstd;

    const int n = blockIdx.x;
    const int t = threadIdx.x;
    const float* Yn = Y + (long)n * FDIM;

    #pragma unroll
    for (int i = 0; i < 16; i++) {
        int idx = t + i * 256;
        int r = idx >> 6, c = idx & 63;
        Ys[r][c]  = Yn[idx];
        Sns[r][c] = Sn[idx];
    }
    __syncthreads();

    const int u  = t >> 2;
    const int c0 = (t & 3) * 16;

    float h[16];
    #pragma unroll
    for (int j = 0; j < 16; j++)
        h[j] = bconv_l[c0 + j] + bconv_l[64 + c0 + j] +
               bconv_l[128 + c0 + j] + bconv_l[192 + c0 + j];

    #pragma unroll 8
    for (int v = 0; v < 64; v++) {
        float s = Sns[u][v];
        #pragma unroll
        for (int j = 0; j < 16; j++) h[j] += s * Ys[v][c0 + j];
    }

    // block mean
    const int lane = t & 31, wid = t >> 5;
    float lsum = 0.0f;
    #pragma unroll
    for (int j = 0; j < 16; j++) lsum += h[j];
    #pragma unroll
    for (int o = 16; o > 0; o >>= 1) lsum += __shfl_xor_sync(0xffffffffu, lsum, o);
    if (lane == 0) red[wid] = lsum;
    __syncthreads();
    if (t == 0) {
        float s = 0.0f;
        #pragma unroll
        for (int i = 0; i < 8; i++) s += red[i];
        s_mu = s * (1.0f / 4096.0f);
    }
    __syncthreads();
    const float mu = s_mu;

    // block variance (two-pass, matches jnp.var)
    float lv = 0.0f;
    #pragma unroll
    for (int j = 0; j < 16; j++) { float d = h[j] - mu; lv += d * d; }
    #pragma unroll
    for (int o = 16; o > 0; o >>= 1) lv += __shfl_xor_sync(0xffffffffu, lv, o);
    if (lane == 0) red[wid] = lv;
    __syncthreads();
    if (t == 0) {
        float s = 0.0f;
        #pragma unroll
        for (int i = 0; i < 8; i++) s += red[i];
        s_rstd = rsqrtf(s * (1.0f / 4096.0f) + LN_EPS);
    }
    __syncthreads();
    const float rstd = s_rstd;

    float* Xn = Xout + (long)n * FDIM + u * 64 + c0;
    const float* gp = gamma_l + u * 64 + c0;
    const float* bp = beta_l  + u * 64 + c0;
    #pragma unroll
    for (int j = 0; j < 16; j++) {
        float v = (h[j] - mu) * rstd * gp[j] + bp[j];
        Xn[j] = fmaxf(v, 0.0f);
    }
}

// ----------- readout: out(2048,64) = X(2048,4096) @ Wl(4096,64) + bl --------
// grid: 2048/16 = 128 blocks, 256 threads
__global__ __launch_bounds__(256)
void final_gemm(const float* __restrict__ X, const float* __restrict__ Wl,
                const float* __restrict__ bl, float* __restrict__ out) {
    __shared__ float Xs[16][128];
    __shared__ float Ws[128][68];
    const int t = threadIdx.x;
    const long m0 = (long)blockIdx.x * 16;
    const int r  = t >> 4;          // 0..15
    const int cq = (t & 15) * 4;    // 0..60

    float acc[4] = {0.f, 0.f, 0.f, 0.f};

    for (int k0 = 0; k0 < FDIM; k0 += 128) {
        #pragma unroll
        for (int i = 0; i < 2; i++) {
            int idx = t + i * 256;              // float4 idx 0..511
            int rr = idx >> 5, cc = (idx & 31) * 4;
            *(float4*)&Xs[rr][cc] = *(const float4*)(X + (m0 + rr) * FDIM + k0 + cc);
        }
        #pragma unroll
        for (int i = 0; i < 8; i++) {
            int idx = t + i * 256;              // float4 idx 0..2047
            int kk = idx >> 4, cc = (idx & 15) * 4;
            float4 v = *(const float4*)(Wl + (long)(k0 + kk) * 64 + cc);
            Ws[kk][cc] = v.x; Ws[kk][cc + 1] = v.y; Ws[kk][cc + 2] = v.z; Ws[kk][cc + 3] = v.w;
        }
        __syncthreads();
        #pragma unroll 16
        for (int kk = 0; kk < 128; kk++) {
            float xv = Xs[r][kk];
            #pragma unroll
            for (int j = 0; j < 4; j++) acc[j] += xv * Ws[kk][cq + j];
        }
        __syncthreads();
    }
    float4 v = make_float4(acc[0] + bl[cq], acc[1] + bl[cq + 1],
                           acc[2] + bl[cq + 2], acc[3] + bl[cq + 3]);
    *(float4*)(out + (m0 + r) * 64 + cq) = v;
}

// ---------------------------------------------------------------------------
extern "C" void kernel_launch(void* const* d_in, const int* in_sizes, int n_in,
                              void* d_out, int out_size) {
    const float* x_in    = (const float*)d_in[0];   // (2048,64,64)
    const int*   sub_adj = (const int*)  d_in[1];   // (64,64)
    const int*   adj     = (const int*)  d_in[2];   // (2048,2048)
    const float* W_convs = (const float*)d_in[3];   // (3,4,64,64)
    const float* b_convs = (const float*)d_in[4];   // (3,4,64)
    const float* ln_g    = (const float*)d_in[5];   // (3,64,64)
    const float* ln_b    = (const float*)d_in[6];   // (3,64,64)
    const float* W_lin   = (const float*)d_in[7];   // (4096,64)
    const float* b_lin   = (const float*)d_in[8];   // (64)
    float* out = (float*)d_out;

    float *Af, *A2, *A3, *X, *B1, *B2, *Y, *Sn;
    cudaGetSymbolAddress((void**)&Af, g_Af);
    cudaGetSymbolAddress((void**)&A2, g_A2);
    cudaGetSymbolAddress((void**)&A3, g_A3);
    cudaGetSymbolAddress((void**)&X,  g_X);
    cudaGetSymbolAddress((void**)&B1, g_B1);
    cudaGetSymbolAddress((void**)&B2, g_B2);
    cudaGetSymbolAddress((void**)&Y,  g_Y);
    cudaGetSymbolAddress((void**)&Sn, g_Sn);

    // precompute: A as float, A^2, A^3, Sn
    cast_i2f<<<(NN * NN) / 256, 256>>>(adj, Af);
    sgemm128<<<dim3(NN / BN, NN / BM), 256>>>(Af, Af, A2, NN, NN, NN);
    sgemm128<<<dim3(NN / BN, NN / BM), 256>>>(A2, Af, A3, NN, NN, NN);
    compute_sn<<<1, 64>>>(sub_adj, Sn);

    const int RB = (NN * MDIM) / 64;   // wgemm blocks = 2048
    for (int l = 0; l < 3; l++) {
        const float* curX = (l == 0) ? x_in : X;
        const float* Wl = W_convs + (long)l * 4 * 4096;

        // Y = curX @ W0
        wgemm64<<<RB, 256>>>(curX, Wl + 0 * 4096, Y, 0);
        // x1 = A @ x ; Y += x1 @ W1
        sgemm128<<<dim3(FDIM / BN, NN / BM), 256>>>(Af, curX, B1, NN, FDIM, NN);
        wgemm64<<<RB, 256>>>(B1, Wl + 1 * 4096, Y, 1);
        // x2 = A^2 @ x1 ; Y += x2 @ W2
        sgemm128<<<dim3(FDIM / BN, NN / BM), 256>>>(A2, B1, B2, NN, FDIM, NN);
        wgemm64<<<RB, 256>>>(B2, Wl + 2 * 4096, Y, 1);
        // x3 = A^3 @ x2 ; Y += x3 @ W3
        sgemm128<<<dim3(FDIM / BN, NN / BM), 256>>>(A3, B2, B1, NN, FDIM, NN);
        wgemm64<<<RB, 256>>>(B1, Wl + 3 * 4096, Y, 1);

        // X = relu(LN(Sn @ Y + sum_i b_i))
        sn_ln_relu<<<NN, 256>>>(Y, Sn,
                                b_convs + (long)l * 256,
                                ln_g + (long)l * 4096,
                                ln_b + (long)l * 4096,
                                X);
    }

    final_gemm<<<NN / 16, 256>>>(X, W_lin, b_lin, out);
}